// round 1
// baseline (speedup 1.0000x reference)
#include <cuda_runtime.h>
#include <math.h>

#define NB   8
#define NT   12
#define BTT  96          // NB*NT
#define NN   10000
#define NH   64
#define NC   2
#define NE   320000
#define ROWS (BTT*NN)    // 960000

// ---------------- scratch (device globals; no allocation allowed) ----------
__device__ float g_T0 [ROWS*NH];   // TC1 output  (Tx0)
__device__ float g_Tx1[ROWS*NH];   // P(Tx0)
__device__ float g_Tx2[ROWS*NH];   // P(Tx1)
__device__ float g_cheb[ROWS*NH];  // relu(cheb out)

__device__ float g_deg[NN];
__device__ float g_dis[NN];
__device__ int   g_cnt[NN];
__device__ int   g_off[NN+1];
__device__ int   g_cur[NN];
__device__ int   g_csr_col[NE];
__device__ float g_csr_w[NE];
__device__ float g_Wcat[192*64];     // cheb fused weights: [W0-W2; W1; 2*W2]
__device__ float g_Wtc2[3*192*64];   // tc2 weights repacked k-major

// ---------------- graph preprocessing --------------------------------------
__global__ void zero_kernel() {
    int i = blockIdx.x*256 + threadIdx.x;
    if (i < NN) { g_deg[i] = 0.f; g_cnt[i] = 0; g_cur[i] = 0; }
}

__global__ void degcnt_kernel(const int* __restrict__ ei, const float* __restrict__ ew) {
    int e = blockIdx.x*256 + threadIdx.x;
    if (e < NE) {
        int r = ei[e];
        atomicAdd(&g_deg[r], ew[e]);
        atomicAdd(&g_cnt[r], 1);
    }
}

__global__ void dis_kernel() {
    int i = blockIdx.x*256 + threadIdx.x;
    if (i < NN) {
        float d = g_deg[i];
        g_dis[i] = d > 0.f ? rsqrtf(d) : 0.f;
    }
}

// exclusive scan of g_cnt -> g_off, single block of 1024 threads
__global__ void scan_kernel() {
    __shared__ int sums[1024];
    int tid = threadIdx.x;
    const int CH = (NN + 1023) / 1024;   // 10
    int base = tid * CH;
    int s = 0;
    for (int i = 0; i < CH; i++) {
        int idx = base + i;
        if (idx < NN) s += g_cnt[idx];
    }
    sums[tid] = s;
    __syncthreads();
    for (int d = 1; d < 1024; d <<= 1) {
        int v = (tid >= d) ? sums[tid - d] : 0;
        __syncthreads();
        sums[tid] += v;
        __syncthreads();
    }
    int run = sums[tid] - s;  // exclusive prefix of this chunk
    for (int i = 0; i < CH; i++) {
        int idx = base + i;
        if (idx < NN) { g_off[idx] = run; run += g_cnt[idx]; }
    }
    if (tid == 1023) g_off[NN] = sums[1023];
}

__global__ void scatter_kernel(const int* __restrict__ ei, const float* __restrict__ ew) {
    int e = blockIdx.x*256 + threadIdx.x;
    if (e < NE) {
        int r = ei[e];
        int c = ei[NE + e];
        int pos = g_off[r] + atomicAdd(&g_cur[r], 1);
        g_csr_col[pos] = c;
        g_csr_w[pos]   = -g_dis[r] * ew[e] * g_dis[c];
    }
}

// ---------------- weight repacking -----------------------------------------
// Wcat[k][j]: k<64 -> W0-W2 ; k<128 -> W1 ; else 2*W2   (cheb_W is [3,64,64])
__global__ void wcat_kernel(const float* __restrict__ W) {
    int idx = blockIdx.x*256 + threadIdx.x;
    if (idx >= 192*64) return;
    int k = idx >> 6, j = idx & 63;
    float v;
    if (k < 64)       v = W[k*64 + j] - W[2*4096 + k*64 + j];
    else if (k < 128) v = W[4096 + (k-64)*64 + j];
    else              v = 2.f * W[2*4096 + (k-128)*64 + j];
    g_Wcat[idx] = v;
}

// g_Wtc2[j][(dt*64+c)][h] = wj[h,c,0,dt]   (wj layout h*192 + c*3 + dt)
__global__ void wtc2_kernel(const float* __restrict__ w1,
                            const float* __restrict__ w2,
                            const float* __restrict__ w3) {
    int idx = blockIdx.x*256 + threadIdx.x;
    if (idx >= 3*192*64) return;
    int j = idx / 12288;
    int r = idx - j*12288;
    int k = r >> 6, h = r & 63;
    int dt = k >> 6;      // 0..2
    int c  = k & 63;
    const float* w = (j == 0) ? w1 : (j == 1) ? w2 : w3;
    g_Wtc2[idx] = w[h*192 + c*3 + dt];
}

// ---------------- TC1: [B,T,N,2] -> relu(P * sigmoid(Q) + R) -> g_T0 -------
__global__ void tc1_kernel(const float* __restrict__ X,
                           const float* __restrict__ w1, const float* __restrict__ b1,
                           const float* __restrict__ w2, const float* __restrict__ b2,
                           const float* __restrict__ w3, const float* __restrict__ b3) {
    __shared__ float s1[384], s2[384], s3[384];
    __shared__ float sb[3][64];
    __shared__ float sx[4][8];
    int tid = threadIdx.x;
    for (int i = tid; i < 384; i += 256) { s1[i] = w1[i]; s2[i] = w2[i]; s3[i] = w3[i]; }
    if (tid < 64) { sb[0][tid] = b1[tid]; sb[1][tid] = b2[tid]; sb[2][tid] = b3[tid]; }
    int bt = blockIdx.y;
    int b = bt / NT, t = bt - b*NT;
    int n0 = blockIdx.x * 4;
    if (tid < 24) {
        int nl = tid / 6, idx = tid % 6;
        int k = idx >> 1, c = idx & 1;
        int tt = t + k - 1;
        float v = 0.f;
        if (tt >= 0 && tt < NT) v = X[(((b*NT + tt)*NN) + (n0 + nl))*NC + c];
        sx[nl][k*2 + c] = v;
    }
    __syncthreads();
    int h = tid & 63, nl = tid >> 6;
    float p = sb[0][h], q = sb[1][h], r = sb[2][h];
    #pragma unroll
    for (int k = 0; k < 3; k++)
        #pragma unroll
        for (int c = 0; c < 2; c++) {
            float xv = sx[nl][k*2 + c];
            int wi = h*6 + c*3 + k;
            p += s1[wi]*xv; q += s2[wi]*xv; r += s3[wi]*xv;
        }
    float sg = 1.f / (1.f + expf(-q));
    float o  = p*sg + r;
    g_T0[(bt*NN + n0 + nl)*NH + h] = fmaxf(o, 0.f);
}

// ---------------- sparse propagation (CSR SpMM) ----------------------------
// dst[bt,n,:] = sum_{e in row n} w_hat[e] * src[bt,col[e],:]
// block = 128 thr = 4 warps; each warp covers 2 bt; lane -> float4 of h
__global__ void prop_kernel(int which) {  // which: 0 = T0->Tx1, 1 = Tx1->Tx2
    const float* src = which ? g_Tx1 : g_T0;
    float*       dst = which ? g_Tx2 : g_Tx1;
    int n    = blockIdx.x;
    int warp = threadIdx.x >> 5, lane = threadIdx.x & 31;
    int bt   = blockIdx.y*8 + warp*2 + (lane >> 4);
    int hq   = lane & 15;
    int e0 = g_off[n], e1 = g_off[n+1];
    const float4* xs = (const float4*)src;
    float4 acc = make_float4(0.f, 0.f, 0.f, 0.f);
    int base = bt * NN;
    for (int e = e0; e < e1; e++) {
        int   c = g_csr_col[e];
        float w = g_csr_w[e];
        float4 v = __ldg(&xs[(base + c)*16 + hq]);
        acc.x += w*v.x; acc.y += w*v.y; acc.z += w*v.z; acc.w += w*v.w;
    }
    ((float4*)dst)[(base + n)*16 + hq] = acc;
}

// ---------------- fused Cheb GEMM + bias + relu ----------------------------
// g_cheb[row,:] = relu( [T0|Tx1|Tx2][row, 0:192] @ Wcat + b )
// BM=64 rows, BN=64 (full), BK=16, 256 thr, 4x4 microtile
__global__ void gemm_cheb(const float* __restrict__ cheb_b) {
    __shared__ alignas(16) float As[16][68];
    __shared__ alignas(16) float Ws[16][64];
    __shared__ float sbias[64];
    int tid = threadIdx.x;
    if (tid < 64) sbias[tid] = cheb_b[tid];
    int row0 = blockIdx.x * 64;
    int tx = tid & 15, ty = tid >> 4;
    int lr = tid >> 2;           // 0..63 (row in tile)
    int lk = (tid & 3) * 4;      // 0,4,8,12 (k quad)
    int wk = tid >> 4, wj = (tid & 15) * 4;
    float acc[4][4];
    #pragma unroll
    for (int i = 0; i < 4; i++)
        #pragma unroll
        for (int j = 0; j < 4; j++) acc[i][j] = 0.f;

    for (int kt = 0; kt < 12; kt++) {
        const float* srcb = (kt < 4) ? g_T0 : (kt < 8) ? g_Tx1 : g_Tx2;
        int ko = (kt & 3) * 16;
        float4 av = *(const float4*)&srcb[(row0 + lr)*64 + ko + lk];
        float4 wv = *(const float4*)&g_Wcat[(kt*16 + wk)*64 + wj];
        __syncthreads();
        As[lk  ][lr] = av.x; As[lk+1][lr] = av.y;
        As[lk+2][lr] = av.z; As[lk+3][lr] = av.w;
        *(float4*)&Ws[wk][wj] = wv;
        __syncthreads();
        #pragma unroll
        for (int kk = 0; kk < 16; kk++) {
            float4 a = *(const float4*)&As[kk][ty*4];
            float4 w = *(const float4*)&Ws[kk][tx*4];
            acc[0][0] += a.x*w.x; acc[0][1] += a.x*w.y; acc[0][2] += a.x*w.z; acc[0][3] += a.x*w.w;
            acc[1][0] += a.y*w.x; acc[1][1] += a.y*w.y; acc[1][2] += a.y*w.z; acc[1][3] += a.y*w.w;
            acc[2][0] += a.z*w.x; acc[2][1] += a.z*w.y; acc[2][2] += a.z*w.z; acc[2][3] += a.z*w.w;
            acc[3][0] += a.w*w.x; acc[3][1] += a.w*w.y; acc[3][2] += a.w*w.z; acc[3][3] += a.w*w.w;
        }
    }
    #pragma unroll
    for (int i = 0; i < 4; i++) {
        int row = row0 + ty*4 + i;
        float4 o;
        o.x = fmaxf(acc[i][0] + sbias[tx*4+0], 0.f);
        o.y = fmaxf(acc[i][1] + sbias[tx*4+1], 0.f);
        o.z = fmaxf(acc[i][2] + sbias[tx*4+2], 0.f);
        o.w = fmaxf(acc[i][3] + sbias[tx*4+3], 0.f);
        *(float4*)&g_cheb[row*64 + tx*4] = o;
    }
}

// ---------------- TC2: gated temporal conv as implicit-im2col GEMM ---------
// per (b,t): A[n, dt*64+c] = g_cheb[b,t+dt-1,n,c] (zero pad), three 192x64 GEMMs
__global__ void tc2_kernel(const float* __restrict__ b1,
                           const float* __restrict__ b2,
                           const float* __restrict__ b3,
                           float* __restrict__ out) {
    __shared__ alignas(16) float As[16][68];
    __shared__ alignas(16) float Ws[3][16][64];
    __shared__ float sb[3][64];
    int tid = threadIdx.x;
    if (tid < 64) { sb[0][tid] = b1[tid]; sb[1][tid] = b2[tid]; sb[2][tid] = b3[tid]; }
    int bt = blockIdx.y, b = bt / NT, t = bt - b*NT;
    int n0 = blockIdx.x * 64;
    int tx = tid & 15, ty = tid >> 4;
    int lr = tid >> 2, lk = (tid & 3) * 4;
    int wk = tid >> 4, wj = (tid & 15) * 4;
    float acc[3][4][4];
    #pragma unroll
    for (int j = 0; j < 3; j++)
        #pragma unroll
        for (int i = 0; i < 4; i++)
            #pragma unroll
            for (int c = 0; c < 4; c++) acc[j][i][c] = 0.f;

    for (int kt = 0; kt < 12; kt++) {
        int dt = kt >> 2;
        int tt = t + dt - 1;
        int c0 = (kt & 3) * 16;
        int n  = n0 + lr;
        float4 av = make_float4(0.f, 0.f, 0.f, 0.f);
        if (tt >= 0 && tt < NT && n < NN)
            av = *(const float4*)&g_cheb[((b*NT + tt)*NN + n)*64 + c0 + lk];
        float4 wv0 = *(const float4*)&g_Wtc2[            (kt*16 + wk)*64 + wj];
        float4 wv1 = *(const float4*)&g_Wtc2[1*12288 +   (kt*16 + wk)*64 + wj];
        float4 wv2 = *(const float4*)&g_Wtc2[2*12288 +   (kt*16 + wk)*64 + wj];
        __syncthreads();
        As[lk  ][lr] = av.x; As[lk+1][lr] = av.y;
        As[lk+2][lr] = av.z; As[lk+3][lr] = av.w;
        *(float4*)&Ws[0][wk][wj] = wv0;
        *(float4*)&Ws[1][wk][wj] = wv1;
        *(float4*)&Ws[2][wk][wj] = wv2;
        __syncthreads();
        #pragma unroll
        for (int kk = 0; kk < 16; kk++) {
            float4 a = *(const float4*)&As[kk][ty*4];
            #pragma unroll
            for (int j = 0; j < 3; j++) {
                float4 w = *(const float4*)&Ws[j][kk][tx*4];
                acc[j][0][0] += a.x*w.x; acc[j][0][1] += a.x*w.y; acc[j][0][2] += a.x*w.z; acc[j][0][3] += a.x*w.w;
                acc[j][1][0] += a.y*w.x; acc[j][1][1] += a.y*w.y; acc[j][1][2] += a.y*w.z; acc[j][1][3] += a.y*w.w;
                acc[j][2][0] += a.z*w.x; acc[j][2][1] += a.z*w.y; acc[j][2][2] += a.z*w.z; acc[j][2][3] += a.z*w.w;
                acc[j][3][0] += a.w*w.x; acc[j][3][1] += a.w*w.y; acc[j][3][2] += a.w*w.z; acc[j][3][3] += a.w*w.w;
            }
        }
    }
    #pragma unroll
    for (int i = 0; i < 4; i++) {
        int n = n0 + ty*4 + i;
        if (n < NN) {
            float4 o;
            float r[4];
            #pragma unroll
            for (int c = 0; c < 4; c++) {
                int h = tx*4 + c;
                float P = acc[0][i][c] + sb[0][h];
                float Q = acc[1][i][c] + sb[1][h];
                float R = acc[2][i][c] + sb[2][h];
                float s = 1.f / (1.f + expf(-Q));
                r[c] = fmaxf(P*s + R, 0.f);
            }
            o.x = r[0]; o.y = r[1]; o.z = r[2]; o.w = r[3];
            *(float4*)&out[((b*NT + t)*NN + n)*64 + tx*4] = o;
        }
    }
}

// ---------------- launcher --------------------------------------------------
extern "C" void kernel_launch(void* const* d_in, const int* in_sizes, int n_in,
                              void* d_out, int out_size) {
    const float* X     = (const float*)d_in[0];
    const int*   ei    = (const int*)  d_in[1];
    const float* ew    = (const float*)d_in[2];
    const float* t1w1  = (const float*)d_in[3];
    const float* t1b1  = (const float*)d_in[4];
    const float* t1w2  = (const float*)d_in[5];
    const float* t1b2  = (const float*)d_in[6];
    const float* t1w3  = (const float*)d_in[7];
    const float* t1b3  = (const float*)d_in[8];
    const float* chebW = (const float*)d_in[9];
    const float* chebB = (const float*)d_in[10];
    const float* t2w1  = (const float*)d_in[11];
    const float* t2b1  = (const float*)d_in[12];
    const float* t2w2  = (const float*)d_in[13];
    const float* t2b2  = (const float*)d_in[14];
    const float* t2w3  = (const float*)d_in[15];
    const float* t2b3  = (const float*)d_in[16];
    float* out = (float*)d_out;

    // graph preprocessing -> CSR with symmetric-normalized negated weights
    zero_kernel   <<<(NN + 255)/256, 256>>>();
    degcnt_kernel <<<(NE + 255)/256, 256>>>(ei, ew);
    dis_kernel    <<<(NN + 255)/256, 256>>>();
    scan_kernel   <<<1, 1024>>>();
    scatter_kernel<<<(NE + 255)/256, 256>>>(ei, ew);

    // weight repack
    wcat_kernel<<<(192*64 + 255)/256, 256>>>(chebW);
    wtc2_kernel<<<(3*192*64 + 255)/256, 256>>>(t2w1, t2w2, t2w3);

    // TC1
    tc1_kernel<<<dim3(NN/4, BTT), 256>>>(X, t1w1, t1b1, t1w2, t1b2, t1w3, t1b3);

    // Chebyshev propagations
    prop_kernel<<<dim3(NN, 12), 128>>>(0);   // T0  -> Tx1
    prop_kernel<<<dim3(NN, 12), 128>>>(1);   // Tx1 -> Tx2

    // fused cheb GEMM + bias + relu
    gemm_cheb<<<ROWS/64, 256>>>(chebB);

    // TC2 -> final output
    tc2_kernel<<<dim3((NN + 63)/64, BTT), 256>>>(t2b1, t2b2, t2b3, out);
}

// round 2
// speedup vs baseline: 1.0355x; 1.0355x over previous
#include <cuda_runtime.h>
#include <math.h>

#define NB   8
#define NT   12
#define BTT  96          // NB*NT
#define NN   10000
#define NH   64
#define NC   2
#define NE   320000
#define ROWS (BTT*NN)    // 960000

typedef unsigned long long u64;

__device__ __forceinline__ void ffma2(u64& d, u64 a, u64 b) {
    asm("fma.rn.f32x2 %0, %1, %2, %0;" : "+l"(d) : "l"(a), "l"(b));
}
__device__ __forceinline__ u64 pack2(float x, float y) {
    u64 r; asm("mov.b64 %0, {%1, %2};" : "=l"(r) : "f"(x), "f"(y)); return r;
}
__device__ __forceinline__ void unpack2(u64 v, float& lo, float& hi) {
    asm("mov.b64 {%0, %1}, %2;" : "=f"(lo), "=f"(hi) : "l"(v));
}

// ---------------- scratch (device globals; no allocation allowed) ----------
__device__ float g_T0 [ROWS*NH];   // TC1 output  (Tx0)
__device__ float g_Tx1[ROWS*NH];   // P(Tx0)
__device__ float g_Tx2[ROWS*NH];   // P(Tx1)
__device__ float g_cheb[ROWS*NH];  // relu(cheb out)

__device__ float g_deg[NN];
__device__ float g_dis[NN];
__device__ int   g_cnt[NN];
__device__ int   g_off[NN+1];
__device__ int   g_cur[NN];
__device__ int   g_csr_col[NE];
__device__ float g_csr_w[NE];
__device__ float g_Wcat[192*64];     // cheb fused weights: [W0-W2; W1; 2*W2]
__device__ float g_Wtc2[3*192*64];   // tc2 weights repacked k-major

// ---------------- graph preprocessing --------------------------------------
__global__ void zero_kernel() {
    int i = blockIdx.x*256 + threadIdx.x;
    if (i < NN) { g_deg[i] = 0.f; g_cnt[i] = 0; g_cur[i] = 0; }
}

__global__ void degcnt_kernel(const int* __restrict__ ei, const float* __restrict__ ew) {
    int e = blockIdx.x*256 + threadIdx.x;
    if (e < NE) {
        int r = ei[e];
        atomicAdd(&g_deg[r], ew[e]);
        atomicAdd(&g_cnt[r], 1);
    }
}

__global__ void dis_kernel() {
    int i = blockIdx.x*256 + threadIdx.x;
    if (i < NN) {
        float d = g_deg[i];
        g_dis[i] = d > 0.f ? rsqrtf(d) : 0.f;
    }
}

// exclusive scan of g_cnt -> g_off, single block of 1024 threads
__global__ void scan_kernel() {
    __shared__ int sums[1024];
    int tid = threadIdx.x;
    const int CH = (NN + 1023) / 1024;   // 10
    int base = tid * CH;
    int s = 0;
    for (int i = 0; i < CH; i++) {
        int idx = base + i;
        if (idx < NN) s += g_cnt[idx];
    }
    sums[tid] = s;
    __syncthreads();
    for (int d = 1; d < 1024; d <<= 1) {
        int v = (tid >= d) ? sums[tid - d] : 0;
        __syncthreads();
        sums[tid] += v;
        __syncthreads();
    }
    int run = sums[tid] - s;  // exclusive prefix of this chunk
    for (int i = 0; i < CH; i++) {
        int idx = base + i;
        if (idx < NN) { g_off[idx] = run; run += g_cnt[idx]; }
    }
    if (tid == 1023) g_off[NN] = sums[1023];
}

__global__ void scatter_kernel(const int* __restrict__ ei, const float* __restrict__ ew) {
    int e = blockIdx.x*256 + threadIdx.x;
    if (e < NE) {
        int r = ei[e];
        int c = ei[NE + e];
        int pos = g_off[r] + atomicAdd(&g_cur[r], 1);
        g_csr_col[pos] = c;
        g_csr_w[pos]   = -g_dis[r] * ew[e] * g_dis[c];
    }
}

// ---------------- weight repacking -----------------------------------------
__global__ void wcat_kernel(const float* __restrict__ W) {
    int idx = blockIdx.x*256 + threadIdx.x;
    if (idx >= 192*64) return;
    int k = idx >> 6, j = idx & 63;
    float v;
    if (k < 64)       v = W[k*64 + j] - W[2*4096 + k*64 + j];
    else if (k < 128) v = W[4096 + (k-64)*64 + j];
    else              v = 2.f * W[2*4096 + (k-128)*64 + j];
    g_Wcat[idx] = v;
}

// g_Wtc2[j][(dt*64+c)][h] = wj[h,c,0,dt]   (wj layout h*192 + c*3 + dt)
__global__ void wtc2_kernel(const float* __restrict__ w1,
                            const float* __restrict__ w2,
                            const float* __restrict__ w3) {
    int idx = blockIdx.x*256 + threadIdx.x;
    if (idx >= 3*192*64) return;
    int j = idx / 12288;
    int r = idx - j*12288;
    int k = r >> 6, h = r & 63;
    int dt = k >> 6;      // 0..2
    int c  = k & 63;
    const float* w = (j == 0) ? w1 : (j == 1) ? w2 : w3;
    g_Wtc2[idx] = w[h*192 + c*3 + dt];
}

// ---------------- TC1 -------------------------------------------------------
__global__ void tc1_kernel(const float* __restrict__ X,
                           const float* __restrict__ w1, const float* __restrict__ b1,
                           const float* __restrict__ w2, const float* __restrict__ b2,
                           const float* __restrict__ w3, const float* __restrict__ b3) {
    __shared__ float s1[384], s2[384], s3[384];
    __shared__ float sb[3][64];
    __shared__ float sx[4][8];
    int tid = threadIdx.x;
    for (int i = tid; i < 384; i += 256) { s1[i] = w1[i]; s2[i] = w2[i]; s3[i] = w3[i]; }
    if (tid < 64) { sb[0][tid] = b1[tid]; sb[1][tid] = b2[tid]; sb[2][tid] = b3[tid]; }
    int bt = blockIdx.y;
    int b = bt / NT, t = bt - b*NT;
    int n0 = blockIdx.x * 4;
    if (tid < 24) {
        int nl = tid / 6, idx = tid % 6;
        int k = idx >> 1, c = idx & 1;
        int tt = t + k - 1;
        float v = 0.f;
        if (tt >= 0 && tt < NT) v = X[(((b*NT + tt)*NN) + (n0 + nl))*NC + c];
        sx[nl][k*2 + c] = v;
    }
    __syncthreads();
    int h = tid & 63, nl = tid >> 6;
    float p = sb[0][h], q = sb[1][h], r = sb[2][h];
    #pragma unroll
    for (int k = 0; k < 3; k++)
        #pragma unroll
        for (int c = 0; c < 2; c++) {
            float xv = sx[nl][k*2 + c];
            int wi = h*6 + c*3 + k;
            p += s1[wi]*xv; q += s2[wi]*xv; r += s3[wi]*xv;
        }
    float sg = 1.f / (1.f + expf(-q));
    float o  = p*sg + r;
    g_T0[(bt*NN + n0 + nl)*NH + h] = fmaxf(o, 0.f);
}

// ---------------- sparse propagation (CSR SpMM) ----------------------------
__global__ void prop_kernel(int which) {  // which: 0 = T0->Tx1, 1 = Tx1->Tx2
    const float* src = which ? g_Tx1 : g_T0;
    float*       dst = which ? g_Tx2 : g_Tx1;
    int n    = blockIdx.x;
    int warp = threadIdx.x >> 5, lane = threadIdx.x & 31;
    int bt   = blockIdx.y*8 + warp*2 + (lane >> 4);
    int hq   = lane & 15;
    int e0 = g_off[n], e1 = g_off[n+1];
    const float4* xs = (const float4*)src;
    float4 acc0 = make_float4(0.f, 0.f, 0.f, 0.f);
    float4 acc1 = make_float4(0.f, 0.f, 0.f, 0.f);
    int base = bt * NN;
    int e = e0;
    for (; e + 1 < e1; e += 2) {
        int   c0 = g_csr_col[e],   c1 = g_csr_col[e+1];
        float w0 = g_csr_w[e],     w1 = g_csr_w[e+1];
        float4 v0 = __ldg(&xs[(base + c0)*16 + hq]);
        float4 v1 = __ldg(&xs[(base + c1)*16 + hq]);
        acc0.x += w0*v0.x; acc0.y += w0*v0.y; acc0.z += w0*v0.z; acc0.w += w0*v0.w;
        acc1.x += w1*v1.x; acc1.y += w1*v1.y; acc1.z += w1*v1.z; acc1.w += w1*v1.w;
    }
    if (e < e1) {
        int   c = g_csr_col[e];
        float w = g_csr_w[e];
        float4 v = __ldg(&xs[(base + c)*16 + hq]);
        acc0.x += w*v.x; acc0.y += w*v.y; acc0.z += w*v.z; acc0.w += w*v.w;
    }
    acc0.x += acc1.x; acc0.y += acc1.y; acc0.z += acc1.z; acc0.w += acc1.w;
    ((float4*)dst)[(base + n)*16 + hq] = acc0;
}

// ---------------- fused Cheb GEMM + bias + relu (FFMA2) --------------------
__global__ void gemm_cheb(const float* __restrict__ cheb_b) {
    __shared__ alignas(16) float As[16][68];
    __shared__ alignas(16) float Ws[16][64];
    __shared__ float sbias[64];
    int tid = threadIdx.x;
    if (tid < 64) sbias[tid] = cheb_b[tid];
    int row0 = blockIdx.x * 64;
    int tx = tid & 15, ty = tid >> 4;
    int lr = tid >> 2;           // 0..63 (row in tile)
    int lk = (tid & 3) * 4;      // 0,4,8,12 (k quad)
    int wk = tid >> 4, wj = (tid & 15) * 4;
    u64 acc2[4][2];
    #pragma unroll
    for (int i = 0; i < 4; i++) { acc2[i][0] = 0ULL; acc2[i][1] = 0ULL; }

    for (int kt = 0; kt < 12; kt++) {
        const float* srcb = (kt < 4) ? g_T0 : (kt < 8) ? g_Tx1 : g_Tx2;
        int ko = (kt & 3) * 16;
        float4 av = *(const float4*)&srcb[(row0 + lr)*64 + ko + lk];
        float4 wv = *(const float4*)&g_Wcat[(kt*16 + wk)*64 + wj];
        __syncthreads();
        As[lk  ][lr] = av.x; As[lk+1][lr] = av.y;
        As[lk+2][lr] = av.z; As[lk+3][lr] = av.w;
        *(float4*)&Ws[wk][wj] = wv;
        __syncthreads();
        #pragma unroll
        for (int kk = 0; kk < 16; kk++) {
            float4 a = *(const float4*)&As[kk][ty*4];
            const u64* w64 = (const u64*)&Ws[kk][tx*4];
            u64 w01 = w64[0], w23 = w64[1];
            u64 a0 = pack2(a.x, a.x);
            u64 a1 = pack2(a.y, a.y);
            u64 a2 = pack2(a.z, a.z);
            u64 a3 = pack2(a.w, a.w);
            ffma2(acc2[0][0], a0, w01); ffma2(acc2[0][1], a0, w23);
            ffma2(acc2[1][0], a1, w01); ffma2(acc2[1][1], a1, w23);
            ffma2(acc2[2][0], a2, w01); ffma2(acc2[2][1], a2, w23);
            ffma2(acc2[3][0], a3, w01); ffma2(acc2[3][1], a3, w23);
        }
    }
    #pragma unroll
    for (int i = 0; i < 4; i++) {
        int row = row0 + ty*4 + i;
        float c0, c1, c2, c3;
        unpack2(acc2[i][0], c0, c1);
        unpack2(acc2[i][1], c2, c3);
        float4 o;
        o.x = fmaxf(c0 + sbias[tx*4+0], 0.f);
        o.y = fmaxf(c1 + sbias[tx*4+1], 0.f);
        o.z = fmaxf(c2 + sbias[tx*4+2], 0.f);
        o.w = fmaxf(c3 + sbias[tx*4+3], 0.f);
        *(float4*)&g_cheb[row*64 + tx*4] = o;
    }
}

// ---------------- TC2: gated temporal conv as implicit-im2col GEMM (FFMA2) -
__global__ void tc2_kernel(const float* __restrict__ b1,
                           const float* __restrict__ b2,
                           const float* __restrict__ b3,
                           float* __restrict__ out) {
    __shared__ alignas(16) float As[16][68];
    __shared__ alignas(16) float Ws[3][16][64];
    __shared__ float sb[3][64];
    int tid = threadIdx.x;
    if (tid < 64) { sb[0][tid] = b1[tid]; sb[1][tid] = b2[tid]; sb[2][tid] = b3[tid]; }
    int bt = blockIdx.y, b = bt / NT, t = bt - b*NT;
    int n0 = blockIdx.x * 64;
    int tx = tid & 15, ty = tid >> 4;
    int lr = tid >> 2, lk = (tid & 3) * 4;
    int wk = tid >> 4, wj = (tid & 15) * 4;
    u64 acc2[3][4][2];
    #pragma unroll
    for (int j = 0; j < 3; j++)
        #pragma unroll
        for (int i = 0; i < 4; i++) { acc2[j][i][0] = 0ULL; acc2[j][i][1] = 0ULL; }

    for (int kt = 0; kt < 12; kt++) {
        int dt = kt >> 2;
        int tt = t + dt - 1;
        int c0 = (kt & 3) * 16;
        int n  = n0 + lr;
        float4 av = make_float4(0.f, 0.f, 0.f, 0.f);
        if (tt >= 0 && tt < NT && n < NN)
            av = *(const float4*)&g_cheb[((b*NT + tt)*NN + n)*64 + c0 + lk];
        float4 wv0 = *(const float4*)&g_Wtc2[            (kt*16 + wk)*64 + wj];
        float4 wv1 = *(const float4*)&g_Wtc2[1*12288 +   (kt*16 + wk)*64 + wj];
        float4 wv2 = *(const float4*)&g_Wtc2[2*12288 +   (kt*16 + wk)*64 + wj];
        __syncthreads();
        As[lk  ][lr] = av.x; As[lk+1][lr] = av.y;
        As[lk+2][lr] = av.z; As[lk+3][lr] = av.w;
        *(float4*)&Ws[0][wk][wj] = wv0;
        *(float4*)&Ws[1][wk][wj] = wv1;
        *(float4*)&Ws[2][wk][wj] = wv2;
        __syncthreads();
        #pragma unroll
        for (int kk = 0; kk < 16; kk++) {
            float4 a = *(const float4*)&As[kk][ty*4];
            u64 a0 = pack2(a.x, a.x);
            u64 a1 = pack2(a.y, a.y);
            u64 a2 = pack2(a.z, a.z);
            u64 a3 = pack2(a.w, a.w);
            #pragma unroll
            for (int j = 0; j < 3; j++) {
                const u64* w64 = (const u64*)&Ws[j][kk][tx*4];
                u64 w01 = w64[0], w23 = w64[1];
                ffma2(acc2[j][0][0], a0, w01); ffma2(acc2[j][0][1], a0, w23);
                ffma2(acc2[j][1][0], a1, w01); ffma2(acc2[j][1][1], a1, w23);
                ffma2(acc2[j][2][0], a2, w01); ffma2(acc2[j][2][1], a2, w23);
                ffma2(acc2[j][3][0], a3, w01); ffma2(acc2[j][3][1], a3, w23);
            }
        }
    }
    #pragma unroll
    for (int i = 0; i < 4; i++) {
        int n = n0 + ty*4 + i;
        if (n < NN) {
            float4 o;
            float r[4];
            #pragma unroll
            for (int c = 0; c < 4; c++) {
                int h = tx*4 + c;
                float P, Q, R, dum;
                float p0, p1, q0, q1, r0, r1;
                unpack2(acc2[0][i][c>>1], p0, p1);
                unpack2(acc2[1][i][c>>1], q0, q1);
                unpack2(acc2[2][i][c>>1], r0, r1);
                P = (c & 1) ? p1 : p0;
                Q = (c & 1) ? q1 : q0;
                R = (c & 1) ? r1 : r0;
                (void)dum;
                P += sb[0][h]; Q += sb[1][h]; R += sb[2][h];
                float s = 1.f / (1.f + expf(-Q));
                r[c] = fmaxf(P*s + R, 0.f);
            }
            o.x = r[0]; o.y = r[1]; o.z = r[2]; o.w = r[3];
            *(float4*)&out[((b*NT + t)*NN + n)*64 + tx*4] = o;
        }
    }
}

// ---------------- launcher --------------------------------------------------
extern "C" void kernel_launch(void* const* d_in, const int* in_sizes, int n_in,
                              void* d_out, int out_size) {
    const float* X     = (const float*)d_in[0];
    const int*   ei    = (const int*)  d_in[1];
    const float* ew    = (const float*)d_in[2];
    const float* t1w1  = (const float*)d_in[3];
    const float* t1b1  = (const float*)d_in[4];
    const float* t1w2  = (const float*)d_in[5];
    const float* t1b2  = (const float*)d_in[6];
    const float* t1w3  = (const float*)d_in[7];
    const float* t1b3  = (const float*)d_in[8];
    const float* chebW = (const float*)d_in[9];
    const float* chebB = (const float*)d_in[10];
    const float* t2w1  = (const float*)d_in[11];
    const float* t2b1  = (const float*)d_in[12];
    const float* t2w2  = (const float*)d_in[13];
    const float* t2b2  = (const float*)d_in[14];
    const float* t2w3  = (const float*)d_in[15];
    const float* t2b3  = (const float*)d_in[16];
    float* out = (float*)d_out;

    // graph preprocessing -> CSR with symmetric-normalized negated weights
    zero_kernel   <<<(NN + 255)/256, 256>>>();
    degcnt_kernel <<<(NE + 255)/256, 256>>>(ei, ew);
    dis_kernel    <<<(NN + 255)/256, 256>>>();
    scan_kernel   <<<1, 1024>>>();
    scatter_kernel<<<(NE + 255)/256, 256>>>(ei, ew);

    // weight repack
    wcat_kernel<<<(192*64 + 255)/256, 256>>>(chebW);
    wtc2_kernel<<<(3*192*64 + 255)/256, 256>>>(t2w1, t2w2, t2w3);

    // TC1
    tc1_kernel<<<dim3(NN/4, BTT), 256>>>(X, t1w1, t1b1, t1w2, t1b2, t1w3, t1b3);

    // Chebyshev propagations
    prop_kernel<<<dim3(NN, 12), 128>>>(0);   // T0  -> Tx1
    prop_kernel<<<dim3(NN, 12), 128>>>(1);   // Tx1 -> Tx2

    // fused cheb GEMM + bias + relu
    gemm_cheb<<<ROWS/64, 256>>>(chebB);

    // TC2 -> final output
    tc2_kernel<<<dim3((NN + 63)/64, BTT), 256>>>(t2b1, t2b2, t2b3, out);
}